// round 5
// baseline (speedup 1.0000x reference)
#include <cuda_runtime.h>
#include <math.h>

#define S_LEN 2048
#define BATCH 2
#define NHEADS 16
#define HDIM 64
#define DIM 1024
#define TDIM 1032

// ---------------- scratch (static device allocations are allowed) ----------
__device__ float g_W[3][DIM * DIM];                         // 12 MB
__device__ float g_qkv[3][BATCH * NHEADS * S_LEN * HDIM];   // 48 MB, layout [b*16+h][s][d]

// ---------------------------------------------------------------------------
// Kernel 1: synthesize the three weight matrices via 9x9 valid conv.
// Block (32,8) computes a 32x32 output tile for all three weight sets,
// sharing one 40x40 template tile in smem.
// ---------------------------------------------------------------------------
__global__ __launch_bounds__(256) void conv_weights_kernel(
    const float* __restrict__ tmpl,
    const float* __restrict__ cw0, const float* __restrict__ cb0,
    const float* __restrict__ cw1, const float* __restrict__ cb1,
    const float* __restrict__ cw2, const float* __restrict__ cb2)
{
    __shared__ float s[40][41];
    __shared__ float scw[3][81];
    __shared__ float scb[3];

    int tid = threadIdx.y * 32 + threadIdx.x;
    int o0 = blockIdx.y * 32;
    int i0 = blockIdx.x * 32;

    for (int idx = tid; idx < 1600; idx += 256) {
        int y = idx / 40, x = idx % 40;
        s[y][x] = tmpl[(o0 + y) * TDIM + (i0 + x)];
    }
    if (tid < 81) {
        scw[0][tid] = cw0[tid];
        scw[1][tid] = cw1[tid];
        scw[2][tid] = cw2[tid];
    }
    if (tid == 0) { scb[0] = cb0[0]; scb[1] = cb1[0]; scb[2] = cb2[0]; }
    __syncthreads();

    int tx = threadIdx.x;
    for (int rr = 0; rr < 4; rr++) {
        int oy = threadIdx.y + rr * 8;
        float a0 = scb[0], a1 = scb[1], a2 = scb[2];
#pragma unroll
        for (int r = 0; r < 9; r++) {
#pragma unroll
            for (int c = 0; c < 9; c++) {
                float t = s[oy + r][tx + c];
                a0 += t * scw[0][r * 9 + c];
                a1 += t * scw[1][r * 9 + c];
                a2 += t * scw[2][r * 9 + c];
            }
        }
        int off = (o0 + oy) * DIM + i0 + tx;
        g_W[0][off] = a0;
        g_W[1][off] = a1;
        g_W[2][off] = a2;
    }
}

// ---------------------------------------------------------------------------
// Kernel 2: projection GEMM  C[m][n] = sum_k X[m][k] * W[n][k] + bias[n]
// M=4096 (= S*B, m = i*B + b), N=K=1024.
// Block tile 128x64, BK=16, 256 threads, 8x4 register tile.
// Epilogue scatters into g_qkv[z] laid out [b*16+h][i][dd]; q (z==0) is
// pre-scaled by 1/8 so attention skips the score scaling.
// ---------------------------------------------------------------------------
__global__ __launch_bounds__(256) void proj_kernel(
    const float* __restrict__ Aq, const float* __restrict__ Ak,
    const float* __restrict__ Av,
    const float* __restrict__ bq, const float* __restrict__ bk,
    const float* __restrict__ bv)
{
    int z = blockIdx.z;
    const float* A    = (z == 0) ? Aq : (z == 1) ? Ak : Av;
    const float* bias = (z == 0) ? bq : (z == 1) ? bk : bv;
    const float* W    = g_W[z];
    float* out        = g_qkv[z];

    __shared__ float As[16][132];
    __shared__ float Bs[16][68];

    int tid = threadIdx.x;
    int m0 = blockIdx.y * 128;
    int n0 = blockIdx.x * 64;
    int lm = tid >> 2;         // 0..63
    int lk = (tid & 3) * 4;    // 0,4,8,12
    int ty = tid >> 4;         // 0..15
    int tx = tid & 15;         // 0..15

    float acc[8][4] = {};

    for (int k0 = 0; k0 < DIM; k0 += 16) {
        float4 a0 = *(const float4*)&A[(m0 + lm) * DIM + k0 + lk];
        float4 a1 = *(const float4*)&A[(m0 + lm + 64) * DIM + k0 + lk];
        float4 b0 = *(const float4*)&W[(n0 + lm) * DIM + k0 + lk];
        __syncthreads();
        As[lk + 0][lm] = a0.x; As[lk + 1][lm] = a0.y;
        As[lk + 2][lm] = a0.z; As[lk + 3][lm] = a0.w;
        As[lk + 0][lm + 64] = a1.x; As[lk + 1][lm + 64] = a1.y;
        As[lk + 2][lm + 64] = a1.z; As[lk + 3][lm + 64] = a1.w;
        Bs[lk + 0][lm] = b0.x; Bs[lk + 1][lm] = b0.y;
        Bs[lk + 2][lm] = b0.z; Bs[lk + 3][lm] = b0.w;
        __syncthreads();

#pragma unroll
        for (int kk = 0; kk < 16; kk++) {
            float4 fa0 = *(const float4*)&As[kk][ty * 8];
            float4 fa1 = *(const float4*)&As[kk][ty * 8 + 4];
            float4 fb  = *(const float4*)&Bs[kk][tx * 4];
            float av[8] = {fa0.x, fa0.y, fa0.z, fa0.w, fa1.x, fa1.y, fa1.z, fa1.w};
            float bv4[4] = {fb.x, fb.y, fb.z, fb.w};
#pragma unroll
            for (int u = 0; u < 8; u++)
#pragma unroll
                for (int v = 0; v < 4; v++)
                    acc[u][v] += av[u] * bv4[v];
        }
    }

    // epilogue: n-tile == one head (64 cols)
    int h = blockIdx.x;   // n0 >> 6
    float4 bfrag = *(const float4*)&bias[n0 + tx * 4];
    float qscale = (z == 0) ? 0.125f : 1.0f;   // 1/sqrt(64) folded into q
#pragma unroll
    for (int u = 0; u < 8; u++) {
        int m = m0 + ty * 8 + u;
        int b = m & 1;
        int i = m >> 1;
        float4 r;
        r.x = (acc[u][0] + bfrag.x) * qscale;
        r.y = (acc[u][1] + bfrag.y) * qscale;
        r.z = (acc[u][2] + bfrag.z) * qscale;
        r.w = (acc[u][3] + bfrag.w) * qscale;
        *(float4*)&out[((b * NHEADS + h) * S_LEN + i) * HDIM + tx * 4] = r;
    }
}

// ---------------------------------------------------------------------------
// Kernel 3: flash attention, fp32. One CTA per (b*h, 64-row q tile).
// 256 threads = 16x16 grid of 4x4 register tiles.
// smem: Qs [64][64] natural, Kt [64][68] transposed (reused as P [64][68]
// natural after S compute), Vs [64][64] natural. 50176 B dynamic.
// ---------------------------------------------------------------------------
#define ATTN_SMEM_BYTES 50176

__global__ __launch_bounds__(256) void attn_kernel(float* __restrict__ out)
{
    extern __shared__ float sm[];
    float* Qs  = sm;                  // 64*64
    float* KPt = sm + 4096;           // 64*68 : Kt (d-major) then P (i-major)
    float* Vs  = sm + 4096 + 4352;    // 64*64

    int tid = threadIdx.x;
    int bh = blockIdx.y;              // b*16 + h
    int qt = blockIdx.x;

    const float* qb = g_qkv[0] + (bh * S_LEN + qt * 64) * HDIM;
    const float* kb = g_qkv[1] + (size_t)bh * S_LEN * HDIM;
    const float* vb = g_qkv[2] + (size_t)bh * S_LEN * HDIM;

    // load Q tile (flat float4 copy, natural layout)
#pragma unroll
    for (int e = 0; e < 4; e++) {
        int idx4 = tid + e * 256;     // 0..1023
        *(float4*)&Qs[idx4 * 4] = *(const float4*)&qb[idx4 * 4];
    }

    int ty = tid >> 4, tx = tid & 15;
    int i0 = ty * 4, j0 = tx * 4;

    float o[4][4] = {};
    float mrow[4] = {-INFINITY, -INFINITY, -INFINITY, -INFINITY};
    float lrow[4] = {};

    int rT = tid >> 4;     // transpose-load row base
    int cq = tid & 15;     // transpose-load col quad

    for (int jt = 0; jt < S_LEN / 64; jt++) {
        __syncthreads();   // previous iteration done with KPt / Vs
        const float* ksrc = kb + jt * 64 * HDIM;
        const float* vsrc = vb + jt * 64 * HDIM;
#pragma unroll
        for (int e = 0; e < 4; e++) {
            int rr = rT + e * 16;
            float4 kv = *(const float4*)&ksrc[rr * HDIM + cq * 4];
            KPt[(cq * 4 + 0) * 68 + rr] = kv.x;
            KPt[(cq * 4 + 1) * 68 + rr] = kv.y;
            KPt[(cq * 4 + 2) * 68 + rr] = kv.z;
            KPt[(cq * 4 + 3) * 68 + rr] = kv.w;
            int idx4 = tid + e * 256;
            *(float4*)&Vs[idx4 * 4] = *(const float4*)&vsrc[idx4 * 4];
        }
        __syncthreads();

        // S = Q K^T   (q already scaled by 1/8)
        float s[4][4] = {};
#pragma unroll 16
        for (int d = 0; d < 64; d++) {
            float a0 = Qs[(i0 + 0) * 64 + d];
            float a1 = Qs[(i0 + 1) * 64 + d];
            float a2 = Qs[(i0 + 2) * 64 + d];
            float a3 = Qs[(i0 + 3) * 64 + d];
            float4 b = *(const float4*)&KPt[d * 68 + j0];
            s[0][0] += a0 * b.x; s[0][1] += a0 * b.y; s[0][2] += a0 * b.z; s[0][3] += a0 * b.w;
            s[1][0] += a1 * b.x; s[1][1] += a1 * b.y; s[1][2] += a1 * b.z; s[1][3] += a1 * b.w;
            s[2][0] += a2 * b.x; s[2][1] += a2 * b.y; s[2][2] += a2 * b.z; s[2][3] += a2 * b.w;
            s[3][0] += a3 * b.x; s[3][1] += a3 * b.y; s[3][2] += a3 * b.z; s[3][3] += a3 * b.w;
        }
        __syncthreads();   // done reading Kt; KPt becomes P

        // online softmax per row (16 lanes own one row group)
#pragma unroll
        for (int u = 0; u < 4; u++) {
            float mt = fmaxf(fmaxf(s[u][0], s[u][1]), fmaxf(s[u][2], s[u][3]));
#pragma unroll
            for (int off = 8; off; off >>= 1)
                mt = fmaxf(mt, __shfl_xor_sync(0xffffffffu, mt, off));
            float mn = fmaxf(mrow[u], mt);
            float p0 = __expf(s[u][0] - mn);
            float p1 = __expf(s[u][1] - mn);
            float p2 = __expf(s[u][2] - mn);
            float p3 = __expf(s[u][3] - mn);
            float lt = p0 + p1 + p2 + p3;
#pragma unroll
            for (int off = 8; off; off >>= 1)
                lt += __shfl_xor_sync(0xffffffffu, lt, off);
            float sc = __expf(mrow[u] - mn);
            mrow[u] = mn;
            lrow[u] = lrow[u] * sc + lt;
            o[u][0] *= sc; o[u][1] *= sc; o[u][2] *= sc; o[u][3] *= sc;
            float4 pv = {p0, p1, p2, p3};
            *(float4*)&KPt[(i0 + u) * 68 + j0] = pv;
        }
        __syncthreads();

        // O += P V
#pragma unroll 16
        for (int j = 0; j < 64; j++) {
            float a0 = KPt[(i0 + 0) * 68 + j];
            float a1 = KPt[(i0 + 1) * 68 + j];
            float a2 = KPt[(i0 + 2) * 68 + j];
            float a3 = KPt[(i0 + 3) * 68 + j];
            float4 b = *(const float4*)&Vs[j * 64 + j0];
            o[0][0] += a0 * b.x; o[0][1] += a0 * b.y; o[0][2] += a0 * b.z; o[0][3] += a0 * b.w;
            o[1][0] += a1 * b.x; o[1][1] += a1 * b.y; o[1][2] += a1 * b.z; o[1][3] += a1 * b.w;
            o[2][0] += a2 * b.x; o[2][1] += a2 * b.y; o[2][2] += a2 * b.z; o[2][3] += a2 * b.w;
            o[3][0] += a3 * b.x; o[3][1] += a3 * b.y; o[3][2] += a3 * b.z; o[3][3] += a3 * b.w;
        }
    }

    // epilogue: out[i][b][h*64+dd]
    int b = bh >> 4, h = bh & 15;
#pragma unroll
    for (int u = 0; u < 4; u++) {
        int ig = qt * 64 + i0 + u;
        float inv = 1.0f / lrow[u];
        float4 r = {o[u][0] * inv, o[u][1] * inv, o[u][2] * inv, o[u][3] * inv};
        *(float4*)&out[(ig * BATCH + b) * DIM + h * HDIM + j0] = r;
    }
}

// ---------------------------------------------------------------------------
extern "C" void kernel_launch(void* const* d_in, const int* in_sizes, int n_in,
                              void* d_out, int out_size)
{
    const float* query = (const float*)d_in[0];
    const float* key   = (const float*)d_in[1];
    const float* value = (const float*)d_in[2];
    const float* tmpl  = (const float*)d_in[3];
    const float* wq_cw = (const float*)d_in[4];
    const float* wq_cb = (const float*)d_in[5];
    const float* wq_b  = (const float*)d_in[6];
    const float* wk_cw = (const float*)d_in[7];
    const float* wk_cb = (const float*)d_in[8];
    const float* wk_b  = (const float*)d_in[9];
    const float* wv_cw = (const float*)d_in[10];
    const float* wv_cb = (const float*)d_in[11];
    const float* wv_b  = (const float*)d_in[12];
    float* out = (float*)d_out;

    cudaFuncSetAttribute(attn_kernel, cudaFuncAttributeMaxDynamicSharedMemorySize,
                         ATTN_SMEM_BYTES);

    conv_weights_kernel<<<dim3(32, 32), dim3(32, 8)>>>(
        tmpl, wq_cw, wq_cb, wk_cw, wk_cb, wv_cw, wv_cb);

    proj_kernel<<<dim3(16, 32, 3), 256>>>(query, key, value, wq_b, wk_b, wv_b);

    attn_kernel<<<dim3(32, 32), 256, ATTN_SMEM_BYTES>>>(out);
}

// round 6
// speedup vs baseline: 1.0246x; 1.0246x over previous
#include <cuda_runtime.h>
#include <math.h>

#define S_LEN 2048
#define BATCH 2
#define NHEADS 16
#define HDIM 64
#define DIM 1024
#define TDIM 1032

typedef unsigned long long ull;

// ---------------- packed f32x2 helpers (Blackwell sm_103a) -----------------
__device__ __forceinline__ ull pk2(float lo, float hi) {
    ull d;
    asm("mov.b64 %0,{%1,%2};" : "=l"(d)
        : "r"(__float_as_uint(lo)), "r"(__float_as_uint(hi)));
    return d;
}
__device__ __forceinline__ void upk2(ull d, float& lo, float& hi) {
    unsigned r0, r1;
    asm("mov.b64 {%0,%1},%2;" : "=r"(r0), "=r"(r1) : "l"(d));
    lo = __uint_as_float(r0); hi = __uint_as_float(r1);
}
__device__ __forceinline__ ull f2fma(ull a, ull b, ull c) {
    ull d;
    asm("fma.rn.f32x2 %0,%1,%2,%3;" : "=l"(d) : "l"(a), "l"(b), "l"(c));
    return d;
}
__device__ __forceinline__ ull f2mul(ull a, ull b) {
    ull d;
    asm("mul.rn.f32x2 %0,%1,%2;" : "=l"(d) : "l"(a), "l"(b));
    return d;
}

// ---------------- scratch (static device allocations are allowed) ----------
__device__ float g_W[3][DIM * DIM];                         // 12 MB
__device__ float g_qkv[3][BATCH * NHEADS * S_LEN * HDIM];   // 48 MB, layout [b*16+h][s][d]

// ---------------------------------------------------------------------------
// Kernel 1: synthesize the three weight matrices via 9x9 valid conv.
// ---------------------------------------------------------------------------
__global__ __launch_bounds__(256, 2) void conv_weights_kernel(
    const float* __restrict__ tmpl,
    const float* __restrict__ cw0, const float* __restrict__ cb0,
    const float* __restrict__ cw1, const float* __restrict__ cb1,
    const float* __restrict__ cw2, const float* __restrict__ cb2)
{
    __shared__ float s[40][41];
    __shared__ float scw[3][81];
    __shared__ float scb[3];

    int tid = threadIdx.y * 32 + threadIdx.x;
    int o0 = blockIdx.y * 32;
    int i0 = blockIdx.x * 32;

    for (int idx = tid; idx < 1600; idx += 256) {
        int y = idx / 40, x = idx % 40;
        s[y][x] = tmpl[(o0 + y) * TDIM + (i0 + x)];
    }
    if (tid < 81) {
        scw[0][tid] = cw0[tid];
        scw[1][tid] = cw1[tid];
        scw[2][tid] = cw2[tid];
    }
    if (tid == 0) { scb[0] = cb0[0]; scb[1] = cb1[0]; scb[2] = cb2[0]; }
    __syncthreads();

    int tx = threadIdx.x;
#pragma unroll 1
    for (int rr = 0; rr < 4; rr++) {
        int oy = threadIdx.y + rr * 8;
        float a0 = scb[0], a1 = scb[1], a2 = scb[2];
#pragma unroll 1
        for (int r = 0; r < 9; r++) {
#pragma unroll
            for (int c = 0; c < 9; c++) {
                float t = s[oy + r][tx + c];
                a0 += t * scw[0][r * 9 + c];
                a1 += t * scw[1][r * 9 + c];
                a2 += t * scw[2][r * 9 + c];
            }
        }
        int off = (o0 + oy) * DIM + i0 + tx;
        g_W[0][off] = a0;
        g_W[1][off] = a1;
        g_W[2][off] = a2;
    }
}

// ---------------------------------------------------------------------------
// Kernel 2: projection GEMM  C[m][n] = sum_k X[m][k] * W[n][k] + bias[n]
// 128x64 block tile, BK=16, 256 threads, 8x4 register tile.
// Inner product uses packed fma.rn.f32x2: m-dim pairs come contiguous from
// the k-major As tile, b values are replicated into both lanes.
// ---------------------------------------------------------------------------
__global__ __launch_bounds__(256) void proj_kernel(
    const float* __restrict__ Aq, const float* __restrict__ Ak,
    const float* __restrict__ Av,
    const float* __restrict__ bq, const float* __restrict__ bk,
    const float* __restrict__ bv)
{
    int z = blockIdx.z;
    const float* A    = (z == 0) ? Aq : (z == 1) ? Ak : Av;
    const float* bias = (z == 0) ? bq : (z == 1) ? bk : bv;
    const float* W    = g_W[z];
    float* out        = g_qkv[z];

    __shared__ __align__(16) float As[16][132];
    __shared__ __align__(16) float Bs[16][68];

    int tid = threadIdx.x;
    int m0 = blockIdx.y * 128;
    int n0 = blockIdx.x * 64;
    int lm = tid >> 2;         // 0..63
    int lk = (tid & 3) * 4;    // 0,4,8,12
    int ty = tid >> 4;         // 0..15
    int tx = tid & 15;         // 0..15

    // acc2[u][v]: m-pair (ty*8+2u, ty*8+2u+1) x column (n0+tx*4+v)
    ull acc2[4][4] = {};

    for (int k0 = 0; k0 < DIM; k0 += 16) {
        float4 a0 = *(const float4*)&A[(m0 + lm) * DIM + k0 + lk];
        float4 a1 = *(const float4*)&A[(m0 + lm + 64) * DIM + k0 + lk];
        float4 b0 = *(const float4*)&W[(n0 + lm) * DIM + k0 + lk];
        __syncthreads();
        As[lk + 0][lm] = a0.x; As[lk + 1][lm] = a0.y;
        As[lk + 2][lm] = a0.z; As[lk + 3][lm] = a0.w;
        As[lk + 0][lm + 64] = a1.x; As[lk + 1][lm + 64] = a1.y;
        As[lk + 2][lm + 64] = a1.z; As[lk + 3][lm + 64] = a1.w;
        Bs[lk + 0][lm] = b0.x; Bs[lk + 1][lm] = b0.y;
        Bs[lk + 2][lm] = b0.z; Bs[lk + 3][lm] = b0.w;
        __syncthreads();

#pragma unroll
        for (int kk = 0; kk < 16; kk++) {
            ulonglong2 a01 = *(const ulonglong2*)&As[kk][ty * 8];
            ulonglong2 a23 = *(const ulonglong2*)&As[kk][ty * 8 + 4];
            float4 fb = *(const float4*)&Bs[kk][tx * 4];
            ull bb[4];
            bb[0] = pk2(fb.x, fb.x);
            bb[1] = pk2(fb.y, fb.y);
            bb[2] = pk2(fb.z, fb.z);
            bb[3] = pk2(fb.w, fb.w);
            ull av[4] = {a01.x, a01.y, a23.x, a23.y};
#pragma unroll
            for (int u = 0; u < 4; u++)
#pragma unroll
                for (int v = 0; v < 4; v++)
                    acc2[u][v] = f2fma(av[u], bb[v], acc2[u][v]);
        }
    }

    // epilogue: n-tile == one head (64 cols)
    int h = blockIdx.x;
    float4 bfrag = *(const float4*)&bias[n0 + tx * 4];
    float qscale = (z == 0) ? 0.125f : 1.0f;   // 1/sqrt(64) folded into q
#pragma unroll
    for (int u = 0; u < 4; u++) {
        float lo[4], hi[4];
#pragma unroll
        for (int v = 0; v < 4; v++) upk2(acc2[u][v], lo[v], hi[v]);
        int mlo = m0 + ty * 8 + 2 * u;
#pragma unroll
        for (int pr = 0; pr < 2; pr++) {
            int m = mlo + pr;
            int b = m & 1;
            int i = m >> 1;
            float* src = pr ? hi : lo;
            float4 r;
            r.x = (src[0] + bfrag.x) * qscale;
            r.y = (src[1] + bfrag.y) * qscale;
            r.z = (src[2] + bfrag.z) * qscale;
            r.w = (src[3] + bfrag.w) * qscale;
            *(float4*)&out[((b * NHEADS + h) * S_LEN + i) * HDIM + tx * 4] = r;
        }
    }
}

// ---------------------------------------------------------------------------
// Kernel 3: flash attention, fp32 with packed f32x2 FMAs.
// One CTA per (b*h, 64-row q tile). 256 threads = 16x16 grid of 4x4 tiles.
// smem: Qt [64][68] d-major (i contiguous -> row pairs free),
//       KPt [64][68]: Kt d-major for S, then Pt j-major (i contiguous) for PV,
//       Vs [64][64] natural. 51200 B dynamic.
// ---------------------------------------------------------------------------
#define ATTN_SMEM_BYTES 51200

__global__ __launch_bounds__(256) void attn_kernel(float* __restrict__ out)
{
    extern __shared__ __align__(16) float sm[];
    float* Qt  = sm;                  // [64 d][68]  (i contiguous)
    float* KPt = sm + 4352;           // Kt [64 d][68], then Pt [64 j][68]
    float* Vs  = sm + 8704;           // [64 j][64]

    int tid = threadIdx.x;
    int bh = blockIdx.y;              // b*16 + h
    int qt = blockIdx.x;

    const float* qb = g_qkv[0] + (bh * S_LEN + qt * 64) * HDIM;
    const float* kb = g_qkv[1] + (size_t)bh * S_LEN * HDIM;
    const float* vb = g_qkv[2] + (size_t)bh * S_LEN * HDIM;

    int rT = tid >> 4;     // 0..15 row base for transpose loads
    int cq = tid & 15;     // col quad

    // load Q transposed into Qt (once per CTA)
#pragma unroll
    for (int e = 0; e < 4; e++) {
        int rr = rT + e * 16;
        float4 qv = *(const float4*)&qb[rr * HDIM + cq * 4];
        Qt[(cq * 4 + 0) * 68 + rr] = qv.x;
        Qt[(cq * 4 + 1) * 68 + rr] = qv.y;
        Qt[(cq * 4 + 2) * 68 + rr] = qv.z;
        Qt[(cq * 4 + 3) * 68 + rr] = qv.w;
    }

    int ty = tid >> 4, tx = tid & 15;
    int i0 = ty * 4, j0 = tx * 4;

    // o2[pu][v]: row pair (i0+2pu, i0+2pu+1) x out-col (j0+v)
    ull o2[2][4] = {};
    float mrow[4] = {-INFINITY, -INFINITY, -INFINITY, -INFINITY};
    float lrow[4] = {};

    for (int jt = 0; jt < S_LEN / 64; jt++) {
        __syncthreads();   // previous iteration done with KPt / Vs (covers Qt 1st iter)
        const float* ksrc = kb + jt * 64 * HDIM;
        const float* vsrc = vb + jt * 64 * HDIM;
#pragma unroll
        for (int e = 0; e < 4; e++) {
            int rr = rT + e * 16;
            float4 kv = *(const float4*)&ksrc[rr * HDIM + cq * 4];
            KPt[(cq * 4 + 0) * 68 + rr] = kv.x;
            KPt[(cq * 4 + 1) * 68 + rr] = kv.y;
            KPt[(cq * 4 + 2) * 68 + rr] = kv.z;
            KPt[(cq * 4 + 3) * 68 + rr] = kv.w;
            int idx4 = tid + e * 256;
            *(float4*)&Vs[idx4 * 4] = *(const float4*)&vsrc[idx4 * 4];
        }
        __syncthreads();

        // S = Q K^T (q pre-scaled by 1/8). s2[pu][v]: row pair x col.
        ull s2[2][4] = {};
#pragma unroll 8
        for (int d = 0; d < 64; d++) {
            ulonglong2 ap = *(const ulonglong2*)&Qt[d * 68 + i0];
            float4 b = *(const float4*)&KPt[d * 68 + j0];
            ull b0 = pk2(b.x, b.x), b1 = pk2(b.y, b.y);
            ull b2 = pk2(b.z, b.z), b3 = pk2(b.w, b.w);
            s2[0][0] = f2fma(ap.x, b0, s2[0][0]);
            s2[0][1] = f2fma(ap.x, b1, s2[0][1]);
            s2[0][2] = f2fma(ap.x, b2, s2[0][2]);
            s2[0][3] = f2fma(ap.x, b3, s2[0][3]);
            s2[1][0] = f2fma(ap.y, b0, s2[1][0]);
            s2[1][1] = f2fma(ap.y, b1, s2[1][1]);
            s2[1][2] = f2fma(ap.y, b2, s2[1][2]);
            s2[1][3] = f2fma(ap.y, b3, s2[1][3]);
        }

        // unpack to scalars for softmax
        float s[4][4];
#pragma unroll
        for (int v = 0; v < 4; v++) {
            upk2(s2[0][v], s[0][v], s[1][v]);
            upk2(s2[1][v], s[2][v], s[3][v]);
        }

        // online softmax per row (16 lanes own one row group)
        float p[4][4], scu[4];
#pragma unroll
        for (int u = 0; u < 4; u++) {
            float mt = fmaxf(fmaxf(s[u][0], s[u][1]), fmaxf(s[u][2], s[u][3]));
#pragma unroll
            for (int off = 8; off; off >>= 1)
                mt = fmaxf(mt, __shfl_xor_sync(0xffffffffu, mt, off));
            float mn = fmaxf(mrow[u], mt);
            p[u][0] = __expf(s[u][0] - mn);
            p[u][1] = __expf(s[u][1] - mn);
            p[u][2] = __expf(s[u][2] - mn);
            p[u][3] = __expf(s[u][3] - mn);
            float lt = p[u][0] + p[u][1] + p[u][2] + p[u][3];
#pragma unroll
            for (int off = 8; off; off >>= 1)
                lt += __shfl_xor_sync(0xffffffffu, lt, off);
            scu[u] = __expf(mrow[u] - mn);
            mrow[u] = mn;
            lrow[u] = lrow[u] * scu[u] + lt;
        }

        // rescale O (packed) while waiting on the barrier
        ull sca = pk2(scu[0], scu[1]);
        ull scb = pk2(scu[2], scu[3]);
#pragma unroll
        for (int v = 0; v < 4; v++) {
            o2[0][v] = f2mul(o2[0][v], sca);
            o2[1][v] = f2mul(o2[1][v], scb);
        }

        __syncthreads();   // everyone done reading Kt; KPt becomes Pt (j-major)
#pragma unroll
        for (int v = 0; v < 4; v++) {
            float4 pv = {p[0][v], p[1][v], p[2][v], p[3][v]};
            *(float4*)&KPt[(j0 + v) * 68 + i0] = pv;
        }
        __syncthreads();

        // O += P V   (Pt j-major: row pairs contiguous)
#pragma unroll 8
        for (int j = 0; j < 64; j++) {
            ulonglong2 ap = *(const ulonglong2*)&KPt[j * 68 + i0];
            float4 b = *(const float4*)&Vs[j * 64 + j0];
            ull b0 = pk2(b.x, b.x), b1 = pk2(b.y, b.y);
            ull b2 = pk2(b.z, b.z), b3 = pk2(b.w, b.w);
            o2[0][0] = f2fma(ap.x, b0, o2[0][0]);
            o2[0][1] = f2fma(ap.x, b1, o2[0][1]);
            o2[0][2] = f2fma(ap.x, b2, o2[0][2]);
            o2[0][3] = f2fma(ap.x, b3, o2[0][3]);
            o2[1][0] = f2fma(ap.y, b0, o2[1][0]);
            o2[1][1] = f2fma(ap.y, b1, o2[1][1]);
            o2[1][2] = f2fma(ap.y, b2, o2[1][2]);
            o2[1][3] = f2fma(ap.y, b3, o2[1][3]);
        }
    }

    // epilogue: out[i][b][h*64+dd]
    float o[4][4];
#pragma unroll
    for (int v = 0; v < 4; v++) {
        upk2(o2[0][v], o[0][v], o[1][v]);
        upk2(o2[1][v], o[2][v], o[3][v]);
    }
    int b = bh >> 4, h = bh & 15;
#pragma unroll
    for (int u = 0; u < 4; u++) {
        int ig = qt * 64 + i0 + u;
        float inv = 1.0f / lrow[u];
        float4 r = {o[u][0] * inv, o[u][1] * inv, o[u][2] * inv, o[u][3] * inv};
        *(float4*)&out[(ig * BATCH + b) * DIM + h * HDIM + j0] = r;
    }
}

// ---------------------------------------------------------------------------
extern "C" void kernel_launch(void* const* d_in, const int* in_sizes, int n_in,
                              void* d_out, int out_size)
{
    const float* query = (const float*)d_in[0];
    const float* key   = (const float*)d_in[1];
    const float* value = (const float*)d_in[2];
    const float* tmpl  = (const float*)d_in[3];
    const float* wq_cw = (const float*)d_in[4];
    const float* wq_cb = (const float*)d_in[5];
    const float* wq_b  = (const float*)d_in[6];
    const float* wk_cw = (const float*)d_in[7];
    const float* wk_cb = (const float*)d_in[8];
    const float* wk_b  = (const float*)d_in[9];
    const float* wv_cw = (const float*)d_in[10];
    const float* wv_cb = (const float*)d_in[11];
    const float* wv_b  = (const float*)d_in[12];
    float* out = (float*)d_out;

    cudaFuncSetAttribute(attn_kernel, cudaFuncAttributeMaxDynamicSharedMemorySize,
                         ATTN_SMEM_BYTES);

    conv_weights_kernel<<<dim3(32, 32), dim3(32, 8)>>>(
        tmpl, wq_cw, wq_cb, wk_cw, wk_cb, wv_cw, wv_cb);

    proj_kernel<<<dim3(16, 32, 3), 256>>>(query, key, value, wq_b, wk_b, wv_b);

    attn_kernel<<<dim3(32, 32), 256, ATTN_SMEM_BYTES>>>(out);
}